// round 2
// baseline (speedup 1.0000x reference)
#include <cuda_runtime.h>

// Fixed problem shape
#define GX 432
#define GY 496
#define NVOX (GX * GY)            // 214272 (GZ = 1)
#define MAXV 160000
#define NPER 200000
#define NPTS (4 * NPER)           // 800000
#define GRIDB 148                 // one block per SM -> single wave, barrier-safe
#define TPB 256
#define NT (GRIDB * TPB)          // 37888
#define CH ((NVOX + GRIDB - 1) / GRIDB)   // 1448 voxels per block
#define IPT ((CH + TPB - 1) / TPB)        // 6 voxels per thread (contiguous)

__device__ int      g_count[NVOX];
__device__ float4   g_sum[NVOX];
__device__ int      g_bsum[GRIDB];
__device__ unsigned g_bar[3];

// Ticket grid barrier: no reset needed across graph replays (unsigned wrap-safe).
// All 148 blocks are co-resident (grid == #SMs), so spinning cannot deadlock.
__device__ __forceinline__ void gridbar(unsigned* cnt) {
    __syncthreads();                       // block done with phase
    if (threadIdx.x == 0) {
        __threadfence();                   // publish phase writes
        unsigned t = atomicAdd(cnt, 1u);
        unsigned base = t - (t % GRIDB);   // start of this launch's round
        while (*(volatile unsigned*)cnt - base < GRIDB) { }
        __threadfence();
    }
    __syncthreads();
}

__global__ void __launch_bounds__(TPB, 1)
fused_kernel(const float* __restrict__ clouds, float4* __restrict__ out) {
    const int tid = threadIdx.x;
    const int blk = blockIdx.x;
    const int gt  = blk * TPB + tid;

    __shared__ int sh[TPB];
    __shared__ int s_prefix, s_total;

    // ---------------- Phase 0: zero scratch ----------------
    for (int v = gt; v < NVOX; v += NT) {
        g_count[v] = 0;
        g_sum[v] = make_float4(0.f, 0.f, 0.f, 0.f);
    }
    gridbar(&g_bar[0]);

    // ---------------- Phase 1: accumulate points ----------------
    for (int p = gt; p < NPTS; p += NT) {
        int b = p / NPER;
        int n = p - b * NPER;
        const float* base = clouds + (size_t)b * 4 * NPER;
        float x = base[n];
        float y = base[NPER + n];
        float z = base[2 * NPER + n];
        float w = base[3 * NPER + n];

        // IEEE divides: bit-exact voxel assignment vs XLA (immune to fast_math)
        int cx = (int)floorf(__fdiv_rn(x,           0.16f));
        int cy = (int)floorf(__fdiv_rn(y + 39.68f,  0.16f));
        int cz = (int)floorf(__fdiv_rn(z + 3.0f,    4.0f));
        if (cx >= 0 && cx < GX && cy >= 0 && cy < GY && cz == 0) {
            int lin = cy * GX + cx;
            atomicAdd(&g_count[lin], 1);           // RED.E.ADD (no return)
            float* s = &g_sum[lin].x;
            asm volatile("red.global.add.v2.f32 [%0], {%1, %2};"
                         :: "l"(s), "f"(x), "f"(y) : "memory");
            asm volatile("red.global.add.v2.f32 [%0], {%1, %2};"
                         :: "l"(s + 2), "f"(z), "f"(w) : "memory");
        }
    }
    gridbar(&g_bar[1]);

    // ---------------- Phase 2a: per-block occupancy count ----------------
    const int v0 = blk * CH;
    const int v1 = (v0 + CH < NVOX) ? v0 + CH : NVOX;
    const int tbase = v0 + tid * IPT;

    int cnt = 0;
#pragma unroll
    for (int i = 0; i < IPT; i++) {
        int v = tbase + i;
        if (v < v1 && g_count[v] > 0) cnt++;
    }
    sh[tid] = cnt;
    __syncthreads();
    for (int off = 128; off > 0; off >>= 1) {
        if (tid < off) sh[tid] += sh[tid + off];
        __syncthreads();
    }
    if (tid == 0) g_bsum[blk] = sh[0];
    gridbar(&g_bar[2]);

    // ---------------- Phase 2b: scan block sums (every block, redundantly) ----
    int bval = (tid < GRIDB) ? g_bsum[tid] : 0;
    sh[tid] = bval;
    __syncthreads();
    int run = bval;
    for (int off = 1; off < TPB; off <<= 1) {
        int t = (tid >= off) ? sh[tid - off] : 0;
        __syncthreads();
        run += t;
        sh[tid] = run;
        __syncthreads();
    }
    if (tid == blk)       s_prefix = run - bval;   // exclusive sum before my block
    if (tid == GRIDB - 1) s_total  = run;          // total occupied voxels
    __syncthreads();

    // ---------------- local scan over this block's voxels + emit -------------
    int occ[IPT];
    int cnt3 = 0;
#pragma unroll
    for (int i = 0; i < IPT; i++) {
        int v = tbase + i;
        occ[i] = (v < v1 && g_count[v] > 0) ? 1 : 0;
        cnt3 += occ[i];
    }
    sh[tid] = cnt3;
    __syncthreads();
    int run2 = cnt3;
    for (int off = 1; off < TPB; off <<= 1) {
        int t = (tid >= off) ? sh[tid - off] : 0;
        __syncthreads();
        run2 += t;
        sh[tid] = run2;
        __syncthreads();
    }
    int rank = s_prefix + (run2 - cnt3);
#pragma unroll
    for (int i = 0; i < IPT; i++) {
        if (occ[i]) {
            if (rank < MAXV) {
                int v = tbase + i;
                float c = (float)g_count[v];
                float4 s = g_sum[v];
                out[rank] = make_float4(__fdiv_rn(s.x, c), __fdiv_rn(s.y, c),
                                        __fdiv_rn(s.z, c), __fdiv_rn(s.w, c));
            }
            rank++;
        }
    }

    // ---------------- tail: zero any unwritten output rows -------------------
    for (int r = s_total + gt; r < MAXV; r += NT)
        out[r] = make_float4(0.f, 0.f, 0.f, 0.f);
}

extern "C" void kernel_launch(void* const* d_in, const int* in_sizes, int n_in,
                              void* d_out, int out_size) {
    const float* clouds = (const float*)d_in[0];
    float4* out = (float4*)d_out;
    fused_kernel<<<GRIDB, TPB>>>(clouds, out);
}

// round 3
// speedup vs baseline: 1.2209x; 1.2209x over previous
#include <cuda_runtime.h>

// Fixed problem shape
#define GX 432
#define GY 496
#define NVOX (GX * GY)            // 214272 (GZ = 1)
#define MAXV 160000
#define NPER 200000
#define NPTS (4 * NPER)           // 800000
#define SBLK 105                  // scan blocks (<=148 SMs -> single wave)
#define TPB 256
#define ITEMS 2048                // voxels per scan block
#define IPT 8                     // voxels per thread

__device__ int      g_count[NVOX];   // zero-initialized at load; kernel restores
__device__ float4   g_sum[NVOX];     // the zero state after consuming it
__device__ int      g_bsum[SBLK];
__device__ unsigned g_bar;

// ---------------------------------------------------------------------------
// Per-point scatter: count + feature sums via L2 reductions. Full occupancy.
// ---------------------------------------------------------------------------
__global__ void __launch_bounds__(TPB)
accum_kernel(const float* __restrict__ clouds) {
    int p = blockIdx.x * TPB + threadIdx.x;
    if (p >= NPTS) return;
    int b = p / NPER;
    int n = p - b * NPER;
    const float* base = clouds + (size_t)b * 4 * NPER;
    float x = base[n];
    float y = base[NPER + n];
    float z = base[2 * NPER + n];
    float w = base[3 * NPER + n];

    // IEEE divides: bit-exact voxel assignment vs XLA (immune to fast_math)
    int cx = (int)floorf(__fdiv_rn(x,          0.16f));
    int cy = (int)floorf(__fdiv_rn(y + 39.68f, 0.16f));
    int cz = (int)floorf(__fdiv_rn(z + 3.0f,   4.0f));
    if (cx < 0 || cx >= GX || cy < 0 || cy >= GY || cz != 0) return;

    int lin = cy * GX + cx;
    atomicAdd(&g_count[lin], 1);               // RED.E.ADD
    float* s = &g_sum[lin].x;
    asm volatile("red.global.add.v2.f32 [%0], {%1, %2};"
                 :: "l"(s), "f"(x), "f"(y) : "memory");
    asm volatile("red.global.add.v2.f32 [%0], {%1, %2};"
                 :: "l"(s + 2), "f"(z), "f"(w) : "memory");
}

// ---------------------------------------------------------------------------
// Fused scan + emit + scratch re-zero. 105 blocks: single wave, barrier-safe.
// ---------------------------------------------------------------------------
__global__ void __launch_bounds__(TPB)
scanemit_kernel(float4* __restrict__ out) {
    const int tid = threadIdx.x;
    const int blk = blockIdx.x;
    const int tbase = blk * ITEMS + tid * IPT;

    __shared__ int sh[TPB];
    __shared__ int s_prefix, s_total;

    // ---- local occupancy flags + thread count ----
    int occ[IPT];
    int cnt = 0;
#pragma unroll
    for (int i = 0; i < IPT; i++) {
        int v = tbase + i;
        occ[i] = (v < NVOX && g_count[v] > 0) ? 1 : 0;
        cnt += occ[i];
    }

    // ---- intra-block inclusive scan (Hillis-Steele) ----
    sh[tid] = cnt;
    __syncthreads();
    int run = cnt;
    for (int off = 1; off < TPB; off <<= 1) {
        int t = (tid >= off) ? sh[tid - off] : 0;
        __syncthreads();
        run += t;
        sh[tid] = run;
        __syncthreads();
    }
    if (tid == TPB - 1) g_bsum[blk] = run;   // block total

    // ---- grid barrier (ticket; wrap-safe across graph replays) ----
    __syncthreads();
    if (tid == 0) {
        __threadfence();
        unsigned t = atomicAdd(&g_bar, 1u);
        unsigned base = t - (t % SBLK);
        while (*(volatile unsigned*)&g_bar - base < SBLK) { }
        __threadfence();
    }
    __syncthreads();

    // ---- redundant scan of the 105 block totals (every block) ----
    int bval = (tid < SBLK) ? g_bsum[tid] : 0;
    sh[tid] = bval;
    __syncthreads();
    int brun = bval;
    for (int off = 1; off < TPB; off <<= 1) {
        int t = (tid >= off) ? sh[tid - off] : 0;
        __syncthreads();
        brun += t;
        sh[tid] = brun;
        __syncthreads();
    }
    if (tid == blk)       s_prefix = brun - bval;
    if (tid == SBLK - 1)  s_total  = brun;
    __syncthreads();

    // ---- emit means; re-zero scratch for the next replay ----
    int rank = s_prefix + (run - cnt);   // exclusive rank of first voxel here
#pragma unroll
    for (int i = 0; i < IPT; i++) {
        int v = tbase + i;
        if (v < NVOX) {
            if (occ[i]) {
                if (rank < MAXV) {
                    float c = (float)g_count[v];
                    float4 s = g_sum[v];
                    out[rank] = make_float4(__fdiv_rn(s.x, c), __fdiv_rn(s.y, c),
                                            __fdiv_rn(s.z, c), __fdiv_rn(s.w, c));
                }
                rank++;
                g_count[v] = 0;
                g_sum[v] = make_float4(0.f, 0.f, 0.f, 0.f);
            }
        }
    }

    // ---- zero any unwritten output rows (usually none: ~209k occupied) ----
    for (int r = s_total + blk * TPB + tid; r < MAXV; r += SBLK * TPB)
        out[r] = make_float4(0.f, 0.f, 0.f, 0.f);
}

// ---------------------------------------------------------------------------
extern "C" void kernel_launch(void* const* d_in, const int* in_sizes, int n_in,
                              void* d_out, int out_size) {
    const float* clouds = (const float*)d_in[0];
    float4* out = (float4*)d_out;
    accum_kernel<<<(NPTS + TPB - 1) / TPB, TPB>>>(clouds);
    scanemit_kernel<<<SBLK, TPB>>>(out);
}

// round 4
// speedup vs baseline: 1.7150x; 1.4047x over previous
#include <cuda_runtime.h>

// Fixed problem shape
#define GX 432
#define GY 496
#define NVOX (GX * GY)            // 214272 (GZ = 1)
#define MAXV 160000
#define NPER 200000
#define NPTS (4 * NPER)           // 800000
#define SBLK 105                  // scan blocks (single wave on 148 SMs)
#define STPB 1024                 // scan threads per block (32 warps)
#define BVOX 2048                 // voxels per scan block (32 warps * 64)

__device__ int      g_count[NVOX];   // zero-initialized at load; kernel restores
__device__ float4   g_sum[NVOX];     // the zero state after consuming it
__device__ int      g_bsum[SBLK];
__device__ unsigned g_bar;

// ---------------------------------------------------------------------------
// Per-point scatter: 2 L2 reduction messages per point (int count + v4 float)
// ---------------------------------------------------------------------------
__global__ void __launch_bounds__(256)
accum_kernel(const float* __restrict__ clouds) {
    int p = blockIdx.x * 256 + threadIdx.x;
    if (p >= NPTS) return;
    int b = p / NPER;
    int n = p - b * NPER;
    const float* base = clouds + (size_t)b * 4 * NPER;
    float x = base[n];
    float y = base[NPER + n];
    float z = base[2 * NPER + n];
    float w = base[3 * NPER + n];

    // IEEE divides: bit-exact voxel assignment vs XLA (immune to fast_math)
    int cx = (int)floorf(__fdiv_rn(x,          0.16f));
    int cy = (int)floorf(__fdiv_rn(y + 39.68f, 0.16f));
    int cz = (int)floorf(__fdiv_rn(z + 3.0f,   4.0f));
    if (cx < 0 || cx >= GX || cy < 0 || cy >= GY || cz != 0) return;

    int lin = cy * GX + cx;
    atomicAdd(&g_count[lin], 1);                       // RED.E.ADD
    asm volatile("red.global.add.v4.f32 [%0], {%1, %2, %3, %4};"
                 :: "l"(&g_sum[lin].x), "f"(x), "f"(y), "f"(z), "f"(w)
                 : "memory");
}

// ---------------------------------------------------------------------------
// Fused compaction: ballot-scan, emit means, re-zero scratch.
// 105 blocks x 1024 threads; warp-coalesced voxel mapping.
// ---------------------------------------------------------------------------
__global__ void __launch_bounds__(STPB)
scanemit_kernel(float4* __restrict__ out) {
    const int tid  = threadIdx.x;
    const int blk  = blockIdx.x;
    const int wid  = tid >> 5;
    const int lane = tid & 31;
    const unsigned lt = (1u << lane) - 1u;
    const int wbase = blk * BVOX + wid * 64;

    __shared__ int s_wsum[32];     // per-warp occupied counts
    __shared__ int s_woff[32];     // exclusive per-warp offsets
    __shared__ int s_prefix, s_total;

    // ---- load counts (coalesced), ballot occupancy ----
    const int v0 = wbase + lane;
    const int v1 = wbase + 32 + lane;
    int c0 = (v0 < NVOX) ? g_count[v0] : 0;
    int c1 = (v1 < NVOX) ? g_count[v1] : 0;
    unsigned b0 = __ballot_sync(0xFFFFFFFFu, c0 > 0);
    unsigned b1 = __ballot_sync(0xFFFFFFFFu, c1 > 0);

    if (lane == 0) s_wsum[wid] = __popc(b0) + __popc(b1);
    __syncthreads();

    // ---- warp 0: exclusive scan of 32 warp sums ----
    if (wid == 0) {
        int v = s_wsum[lane];
        int s = v;
        #pragma unroll
        for (int off = 1; off < 32; off <<= 1) {
            int t = __shfl_up_sync(0xFFFFFFFFu, s, off);
            if (lane >= off) s += t;
        }
        s_woff[lane] = s - v;                 // exclusive
        if (lane == 31) g_bsum[blk] = s;      // block total
    }

    // ---- grid barrier (ticket; wrap-safe across graph replays) ----
    __syncthreads();
    if (tid == 0) {
        __threadfence();
        unsigned t = atomicAdd(&g_bar, 1u);
        unsigned base = t - (t % SBLK);
        while (*(volatile unsigned*)&g_bar - base < SBLK) { }
        __threadfence();
    }
    __syncthreads();

    // ---- warp 0: redundant scan of the 105 block totals ----
    if (wid == 0) {
        int carry = 0;
        #pragma unroll
        for (int i = 0; i < 4; i++) {
            int idx = i * 32 + lane;
            int v = (idx < SBLK) ? g_bsum[idx] : 0;
            int s = v;
            #pragma unroll
            for (int off = 1; off < 32; off <<= 1) {
                int t = __shfl_up_sync(0xFFFFFFFFu, s, off);
                if (lane >= off) s += t;
            }
            if (idx == blk)      s_prefix = carry + s - v;   // exclusive
            if (idx == SBLK - 1) s_total  = carry + s;
            carry += __shfl_sync(0xFFFFFFFFu, s, 31);
        }
    }
    __syncthreads();

    // ---- emit means (ballot-compacted ranks); re-zero scratch ----
    int wrank = s_prefix + s_woff[wid];
    const float4 fz = make_float4(0.f, 0.f, 0.f, 0.f);

    if (c0 > 0) {
        int r = wrank + __popc(b0 & lt);
        if (r < MAXV) {
            float c = (float)c0;
            float4 s = g_sum[v0];
            out[r] = make_float4(__fdiv_rn(s.x, c), __fdiv_rn(s.y, c),
                                 __fdiv_rn(s.z, c), __fdiv_rn(s.w, c));
        }
        g_count[v0] = 0;
        g_sum[v0] = fz;
    }
    wrank += __popc(b0);
    if (c1 > 0) {
        int r = wrank + __popc(b1 & lt);
        if (r < MAXV) {
            float c = (float)c1;
            float4 s = g_sum[v1];
            out[r] = make_float4(__fdiv_rn(s.x, c), __fdiv_rn(s.y, c),
                                 __fdiv_rn(s.z, c), __fdiv_rn(s.w, c));
        }
        g_count[v1] = 0;
        g_sum[v1] = fz;
    }

    // ---- zero any unwritten output rows (none in practice: ~209k occupied) --
    for (int r = s_total + blk * STPB + tid; r < MAXV; r += SBLK * STPB)
        out[r] = fz;
}

// ---------------------------------------------------------------------------
extern "C" void kernel_launch(void* const* d_in, const int* in_sizes, int n_in,
                              void* d_out, int out_size) {
    const float* clouds = (const float*)d_in[0];
    float4* out = (float4*)d_out;
    accum_kernel<<<(NPTS + 255) / 256, 256>>>(clouds);
    scanemit_kernel<<<SBLK, STPB>>>(out);
}